// round 4
// baseline (speedup 1.0000x reference)
#include <cuda_runtime.h>
#include <math.h>

#define HD 128
#define TILE 64      // edges per block tile (32 pairs)
#define NTILE 64     // nodes per block tile (pre)
#define OTILE 32     // nodes per block tile (out)
#define NMAX 20000
#define EMAX 640000

// Scratch (device globals: allocation-free)
__device__ float g_P[NMAX * HD];
__device__ float g_Q[NMAX * HD];
__device__ float g_mi[NMAX * HD];
__device__ float g_psum[NMAX * 3];
__device__ float g_cnt[NMAX];
// duplicated weights for f32x2 GEMV: Wd[k][2j] = Wd[k][2j+1] = W[k][j]
__device__ float g_W2d[HD * 2 * HD];   // eW2 duplicated, 128 KB
__device__ float g_C1d[HD * 2 * HD];   // cW1 duplicated, 128 KB

__device__ __forceinline__ float silu(float x) {
    float hx = 0.5f * x;
    float t;
    asm("tanh.approx.f32 %0, %1;" : "=f"(t) : "f"(hx));
    return fmaf(hx, t, hx);          // 0.5x*(1+tanh(0.5x)) = x*sigmoid(x)
}

__device__ __forceinline__ void fma2(unsigned long long& acc,
                                     unsigned long long a, unsigned long long b) {
    asm("fma.rn.f32x2 %0, %1, %2, %0;" : "+l"(acc) : "l"(a), "l"(b));
}

__device__ __forceinline__ void lds_v2u64(unsigned long long& a, unsigned long long& b,
                                          unsigned addr) {
    asm volatile("ld.shared.v2.b64 {%0, %1}, [%2];" : "=l"(a), "=l"(b) : "r"(addr));
}

__device__ __forceinline__ void ldg_v2u64(unsigned long long& a, unsigned long long& b,
                                          const float* p) {
    asm volatile("ld.global.nc.v2.b64 {%0, %1}, [%2];" : "=l"(a), "=l"(b) : "l"(p));
}

__device__ __forceinline__ unsigned smem_u32(const void* p) {
    unsigned r;
    asm("{ .reg .u64 t; cvta.to.shared.u64 t, %1; cvt.u32.u64 %0, t; }"
        : "=r"(r) : "l"(p));
    return r;
}

__device__ __forceinline__ float f2lo(unsigned long long v) {
    return __uint_as_float((unsigned)(v & 0xFFFFFFFFull));
}
__device__ __forceinline__ float f2hi(unsigned long long v) {
    return __uint_as_float((unsigned)(v >> 32));
}

// ---------------------------------------------------------------- zero + weight dup
__global__ void zero_kernel(int N) {
    int i = blockIdx.x * blockDim.x + threadIdx.x;
    if (i < N * HD) g_mi[i] = 0.0f;
    int j = i - N * HD;
    if (j >= 0 && j < N * 3) g_psum[j] = 0.0f;
    int k = i - N * (HD + 3);
    if (k >= 0 && k < N) g_cnt[k] = 0.0f;
}

__global__ void dup_weights_kernel(const float* __restrict__ eW2,
                                   const float* __restrict__ cW1) {
    int i = blockIdx.x * blockDim.x + threadIdx.x;
    if (i < HD * HD) {
        int k = i >> 7, j = i & 127;
        float w = eW2[i];
        g_W2d[k * 256 + 2 * j]     = w;
        g_W2d[k * 256 + 2 * j + 1] = w;
        float c = cW1[i];
        g_C1d[k * 256 + 2 * j]     = c;
        g_C1d[k * 256 + 2 * j + 1] = c;
    }
}

// ---------------------------------------------------------------- node pre:
// P = h @ eW1[0:128,:], Q = h @ eW1[128:256,:]
__global__ __launch_bounds__(256) void node_pre_kernel(
    const float* __restrict__ h, const float* __restrict__ eW1, int N)
{
    __shared__ float sH[NTILE * HD];   // 32 KB

    const int base = blockIdx.x * NTILE;

    for (int idx = threadIdx.x; idx < NTILE * HD; idx += 256) {
        int n = base + (idx >> 7);
        sH[idx] = (n < N) ? h[(size_t)n * HD + (idx & 127)] : 0.0f;
    }
    __syncthreads();

    const int lane = threadIdx.x & 31;
    const int warp = threadIdx.x >> 5;
    const int jj = lane * 4;
    const int e0 = warp * 8;

    #pragma unroll
    for (int half = 0; half < 2; half++) {
        const float* W = eW1 + (size_t)half * HD * HD;
        float* out = half ? g_Q : g_P;

        float acc[8][4];
        #pragma unroll
        for (int e = 0; e < 8; e++)
            #pragma unroll
            for (int i = 0; i < 4; i++) acc[e][i] = 0.f;

        for (int k = 0; k < HD; k += 4) {
            float4 w0 = *(const float4*)&W[(k + 0) * HD + jj];
            float4 w1 = *(const float4*)&W[(k + 1) * HD + jj];
            float4 w2 = *(const float4*)&W[(k + 2) * HD + jj];
            float4 w3 = *(const float4*)&W[(k + 3) * HD + jj];
            #pragma unroll
            for (int e = 0; e < 8; e++) {
                float4 tv = *(const float4*)&sH[(e0 + e) * HD + k];
                acc[e][0] = fmaf(tv.x, w0.x, acc[e][0]);
                acc[e][1] = fmaf(tv.x, w0.y, acc[e][1]);
                acc[e][2] = fmaf(tv.x, w0.z, acc[e][2]);
                acc[e][3] = fmaf(tv.x, w0.w, acc[e][3]);
                acc[e][0] = fmaf(tv.y, w1.x, acc[e][0]);
                acc[e][1] = fmaf(tv.y, w1.y, acc[e][1]);
                acc[e][2] = fmaf(tv.y, w1.z, acc[e][2]);
                acc[e][3] = fmaf(tv.y, w1.w, acc[e][3]);
                acc[e][0] = fmaf(tv.z, w2.x, acc[e][0]);
                acc[e][1] = fmaf(tv.z, w2.y, acc[e][1]);
                acc[e][2] = fmaf(tv.z, w2.z, acc[e][2]);
                acc[e][3] = fmaf(tv.z, w2.w, acc[e][3]);
                acc[e][0] = fmaf(tv.w, w3.x, acc[e][0]);
                acc[e][1] = fmaf(tv.w, w3.y, acc[e][1]);
                acc[e][2] = fmaf(tv.w, w3.z, acc[e][2]);
                acc[e][3] = fmaf(tv.w, w3.w, acc[e][3]);
            }
        }
        #pragma unroll
        for (int e = 0; e < 8; e++) {
            int n = base + e0 + e;
            if (n < N) {
                float4 o = make_float4(acc[e][0], acc[e][1], acc[e][2], acc[e][3]);
                *(float4*)&out[(size_t)n * HD + jj] = o;
            }
        }
    }
}

// ---------------------------------------------------------------- edge kernel (f32x2)
// Tp[pair][k] holds (val_e0, val_e1) packed; each warp owns 4 pairs (8 edges).
__global__ __launch_bounds__(256) void edge_kernel(
    const float* __restrict__ pos,
    const int* __restrict__ eidx,
    const float* __restrict__ eW1, const float* __restrict__ eb1,
    const float* __restrict__ eb2,
    const float* __restrict__ cb1, const float* __restrict__ cW2,
    int N, int E)
{
    __shared__ float2 Tp[(TILE / 2) * HD];   // 32 KB, pair-packed; T then M in place
    __shared__ float sSq[TILE], sCw[TILE], sDx[TILE], sDy[TILE], sDz[TILE];
    __shared__ int   sR[TILE], sC[TILE];

    const int base = blockIdx.x * TILE;

    if (threadIdx.x < TILE) {
        int e = base + threadIdx.x;
        int r = 0, c = 0;
        float dx = 0.f, dy = 0.f, dz = 0.f, sq = 0.f;
        if (e < E) {
            r = eidx[e];
            c = eidx[E + e];
            dx = pos[r * 3 + 0] - pos[c * 3 + 0];
            dy = pos[r * 3 + 1] - pos[c * 3 + 1];
            dz = pos[r * 3 + 2] - pos[c * 3 + 2];
            sq = dx * dx + dy * dy + dz * dz;
        }
        sR[threadIdx.x] = r; sC[threadIdx.x] = c;
        sSq[threadIdx.x] = sq;
        sDx[threadIdx.x] = dx; sDy[threadIdx.x] = dy; sDz[threadIdx.x] = dz;
    }
    __syncthreads();

    // assembly: Tp[p][k] = (silu(x_{2p,k}), silu(x_{2p+1,k}))
    const float* w256 = eW1 + 256 * HD;
    for (int idx = threadIdx.x; idx < (TILE / 2) * HD; idx += 256) {
        int p = idx >> 7, k = idx & 127;
        int ea = 2 * p, eb = 2 * p + 1;
        float wk = w256[k], bk = eb1[k];
        float x0 = g_P[(size_t)sR[ea] * HD + k] + g_Q[(size_t)sC[ea] * HD + k]
                 + sSq[ea] * wk + bk;
        float x1 = g_P[(size_t)sR[eb] * HD + k] + g_Q[(size_t)sC[eb] * HD + k]
                 + sSq[eb] * wk + bk;
        Tp[idx] = make_float2(silu(x0), silu(x1));
    }
    __syncthreads();

    const int lane = threadIdx.x & 31;
    const int warp = threadIdx.x >> 5;
    const int jj = lane * 4;           // 4 output cols per lane
    const int p0 = warp * 4;           // 4 pairs (8 edges) per warp

    const unsigned tp0 = smem_u32(Tp) + (unsigned)(p0 * HD) * 8u;

    // ---------------- GEMV 1: M = silu(T @ eW2 + eb2), in place (pair-packed)
    {
        unsigned long long acc[4][4];
        #pragma unroll
        for (int p = 0; p < 4; p++)
            #pragma unroll
            for (int c = 0; c < 4; c++) acc[p][c] = 0ull;

        #pragma unroll 4
        for (int kk = 0; kk < HD; kk += 2) {
            unsigned long long wa0, wa1, wa2, wa3, wb0, wb1, wb2, wb3;
            ldg_v2u64(wa0, wa1, &g_W2d[(kk + 0) * 256 + 2 * jj]);
            ldg_v2u64(wa2, wa3, &g_W2d[(kk + 0) * 256 + 2 * jj + 4]);
            ldg_v2u64(wb0, wb1, &g_W2d[(kk + 1) * 256 + 2 * jj]);
            ldg_v2u64(wb2, wb3, &g_W2d[(kk + 1) * 256 + 2 * jj + 4]);
            #pragma unroll
            for (int p = 0; p < 4; p++) {
                unsigned long long t0, t1;
                lds_v2u64(t0, t1, tp0 + (unsigned)(p * HD + kk) * 8u);
                fma2(acc[p][0], t0, wa0);
                fma2(acc[p][1], t0, wa1);
                fma2(acc[p][2], t0, wa2);
                fma2(acc[p][3], t0, wa3);
                fma2(acc[p][0], t1, wb0);
                fma2(acc[p][1], t1, wb1);
                fma2(acc[p][2], t1, wb2);
                fma2(acc[p][3], t1, wb3);
            }
        }
        __syncwarp();   // all lanes finished reading T rows of this warp
        float4 b2 = *(const float4*)&eb2[jj];
        float bv[4] = { b2.x, b2.y, b2.z, b2.w };
        #pragma unroll
        for (int p = 0; p < 4; p++) {
            #pragma unroll
            for (int c = 0; c < 4; c++) {
                float m0 = silu(f2lo(acc[p][c]) + bv[c]);
                float m1 = silu(f2hi(acc[p][c]) + bv[c]);
                Tp[(p0 + p) * HD + jj + c] = make_float2(m0, m1);
            }
        }
    }
    __syncwarp();

    // ---------------- GEMV 2: cw = silu(M @ cW1 + cb1) . cW2
    {
        unsigned long long acc[4][4];
        #pragma unroll
        for (int p = 0; p < 4; p++)
            #pragma unroll
            for (int c = 0; c < 4; c++) acc[p][c] = 0ull;

        #pragma unroll 4
        for (int kk = 0; kk < HD; kk += 2) {
            unsigned long long wa0, wa1, wa2, wa3, wb0, wb1, wb2, wb3;
            ldg_v2u64(wa0, wa1, &g_C1d[(kk + 0) * 256 + 2 * jj]);
            ldg_v2u64(wa2, wa3, &g_C1d[(kk + 0) * 256 + 2 * jj + 4]);
            ldg_v2u64(wb0, wb1, &g_C1d[(kk + 1) * 256 + 2 * jj]);
            ldg_v2u64(wb2, wb3, &g_C1d[(kk + 1) * 256 + 2 * jj + 4]);
            #pragma unroll
            for (int p = 0; p < 4; p++) {
                unsigned long long t0, t1;
                lds_v2u64(t0, t1, tp0 + (unsigned)(p * HD + kk) * 8u);
                fma2(acc[p][0], t0, wa0);
                fma2(acc[p][1], t0, wa1);
                fma2(acc[p][2], t0, wa2);
                fma2(acc[p][3], t0, wa3);
                fma2(acc[p][0], t1, wb0);
                fma2(acc[p][1], t1, wb1);
                fma2(acc[p][2], t1, wb2);
                fma2(acc[p][3], t1, wb3);
            }
        }
        float4 cb  = *(const float4*)&cb1[jj];
        float4 cw2 = *(const float4*)&cW2[jj];
        float cbv[4]  = { cb.x, cb.y, cb.z, cb.w };
        float cw2v[4] = { cw2.x, cw2.y, cw2.z, cw2.w };
        #pragma unroll
        for (int p = 0; p < 4; p++) {
            float s0 = 0.f, s1 = 0.f;
            #pragma unroll
            for (int c = 0; c < 4; c++) {
                s0 += silu(f2lo(acc[p][c]) + cbv[c]) * cw2v[c];
                s1 += silu(f2hi(acc[p][c]) + cbv[c]) * cw2v[c];
            }
            #pragma unroll
            for (int off = 16; off > 0; off >>= 1) {
                s0 += __shfl_xor_sync(0xFFFFFFFFu, s0, off);
                s1 += __shfl_xor_sync(0xFFFFFFFFu, s1, off);
            }
            if (lane == 0) {
                sCw[2 * (p0 + p)]     = s0;
                sCw[2 * (p0 + p) + 1] = s1;
            }
        }
    }
    __syncthreads();

    // scatter messages (Tp now holds M, pair-packed)
    for (int idx = threadIdx.x; idx < (TILE / 2) * HD; idx += 256) {
        int p = idx >> 7, k = idx & 127;
        float2 mv = Tp[idx];
        int ea = 2 * p, eb = 2 * p + 1;
        if (base + ea < E) atomicAdd(&g_mi[(size_t)sR[ea] * HD + k], mv.x);
        if (base + eb < E) atomicAdd(&g_mi[(size_t)sR[eb] * HD + k], mv.y);
    }
    // scatter pos updates + counts
    if (threadIdx.x < TILE) {
        int e = threadIdx.x;
        if (base + e < E) {
            float inv = rsqrtf(sSq[e] + 1e-8f);
            float w = sCw[e] * inv;
            int r = sR[e];
            atomicAdd(&g_psum[r * 3 + 0], sDx[e] * w);
            atomicAdd(&g_psum[r * 3 + 1], sDy[e] * w);
            atomicAdd(&g_psum[r * 3 + 2], sDz[e] * w);
            atomicAdd(&g_cnt[r], 1.0f);
        }
    }
}

// ---------------------------------------------------------------- node out MLP + pos
__global__ __launch_bounds__(256) void node_out_kernel(
    const float* __restrict__ h, const float* __restrict__ pos,
    const float* __restrict__ nW1, const float* __restrict__ nb1,
    const float* __restrict__ nW2, const float* __restrict__ nb2,
    float* __restrict__ outH, float* __restrict__ outP, int N)
{
    __shared__ float sX[OTILE * 2 * HD];   // 32 KB

    const int base = blockIdx.x * OTILE;

    for (int idx = threadIdx.x; idx < OTILE * 2 * HD; idx += 256) {
        int n = base + (idx >> 8);
        int j = idx & 255;
        float v = 0.f;
        if (n < N)
            v = (j < HD) ? h[(size_t)n * HD + j] : g_mi[(size_t)n * HD + (j - HD)];
        sX[idx] = v;
    }
    __syncthreads();

    const int lane = threadIdx.x & 31;
    const int warp = threadIdx.x >> 5;
    const int jj = lane * 4;
    const int e0 = warp * 4;

    // GEMV 1: U = silu([h|m] @ nW1 + nb1), in-place into cols [0,128)
    {
        float acc[4][4];
        #pragma unroll
        for (int e = 0; e < 4; e++)
            #pragma unroll
            for (int i = 0; i < 4; i++) acc[e][i] = 0.f;

        for (int k = 0; k < 2 * HD; k += 4) {
            float4 w0 = *(const float4*)&nW1[(k + 0) * HD + jj];
            float4 w1 = *(const float4*)&nW1[(k + 1) * HD + jj];
            float4 w2 = *(const float4*)&nW1[(k + 2) * HD + jj];
            float4 w3 = *(const float4*)&nW1[(k + 3) * HD + jj];
            #pragma unroll
            for (int e = 0; e < 4; e++) {
                float4 tv = *(const float4*)&sX[(e0 + e) * 2 * HD + k];
                acc[e][0] = fmaf(tv.x, w0.x, acc[e][0]);
                acc[e][1] = fmaf(tv.x, w0.y, acc[e][1]);
                acc[e][2] = fmaf(tv.x, w0.z, acc[e][2]);
                acc[e][3] = fmaf(tv.x, w0.w, acc[e][3]);
                acc[e][0] = fmaf(tv.y, w1.x, acc[e][0]);
                acc[e][1] = fmaf(tv.y, w1.y, acc[e][1]);
                acc[e][2] = fmaf(tv.y, w1.z, acc[e][2]);
                acc[e][3] = fmaf(tv.y, w1.w, acc[e][3]);
                acc[e][0] = fmaf(tv.z, w2.x, acc[e][0]);
                acc[e][1] = fmaf(tv.z, w2.y, acc[e][1]);
                acc[e][2] = fmaf(tv.z, w2.z, acc[e][2]);
                acc[e][3] = fmaf(tv.z, w2.w, acc[e][3]);
                acc[e][0] = fmaf(tv.w, w3.x, acc[e][0]);
                acc[e][1] = fmaf(tv.w, w3.y, acc[e][1]);
                acc[e][2] = fmaf(tv.w, w3.z, acc[e][2]);
                acc[e][3] = fmaf(tv.w, w3.w, acc[e][3]);
            }
        }
        __syncwarp();
        float4 b1 = *(const float4*)&nb1[jj];
        #pragma unroll
        for (int e = 0; e < 4; e++) {
            float4 u;
            u.x = silu(acc[e][0] + b1.x);
            u.y = silu(acc[e][1] + b1.y);
            u.z = silu(acc[e][2] + b1.z);
            u.w = silu(acc[e][3] + b1.w);
            *(float4*)&sX[(e0 + e) * 2 * HD + jj] = u;
        }
    }
    __syncwarp();

    // GEMV 2: out = h + U @ nW2 + nb2
    {
        float acc[4][4];
        #pragma unroll
        for (int e = 0; e < 4; e++)
            #pragma unroll
            for (int i = 0; i < 4; i++) acc[e][i] = 0.f;

        for (int k = 0; k < HD; k += 4) {
            float4 w0 = *(const float4*)&nW2[(k + 0) * HD + jj];
            float4 w1 = *(const float4*)&nW2[(k + 1) * HD + jj];
            float4 w2 = *(const float4*)&nW2[(k + 2) * HD + jj];
            float4 w3 = *(const float4*)&nW2[(k + 3) * HD + jj];
            #pragma unroll
            for (int e = 0; e < 4; e++) {
                float4 tv = *(const float4*)&sX[(e0 + e) * 2 * HD + k];
                acc[e][0] = fmaf(tv.x, w0.x, acc[e][0]);
                acc[e][1] = fmaf(tv.x, w0.y, acc[e][1]);
                acc[e][2] = fmaf(tv.x, w0.z, acc[e][2]);
                acc[e][3] = fmaf(tv.x, w0.w, acc[e][3]);
                acc[e][0] = fmaf(tv.y, w1.x, acc[e][0]);
                acc[e][1] = fmaf(tv.y, w1.y, acc[e][1]);
                acc[e][2] = fmaf(tv.y, w1.z, acc[e][2]);
                acc[e][3] = fmaf(tv.y, w1.w, acc[e][3]);
                acc[e][0] = fmaf(tv.z, w2.x, acc[e][0]);
                acc[e][1] = fmaf(tv.z, w2.y, acc[e][1]);
                acc[e][2] = fmaf(tv.z, w2.z, acc[e][2]);
                acc[e][3] = fmaf(tv.z, w2.w, acc[e][3]);
                acc[e][0] = fmaf(tv.w, w3.x, acc[e][0]);
                acc[e][1] = fmaf(tv.w, w3.y, acc[e][1]);
                acc[e][2] = fmaf(tv.w, w3.z, acc[e][2]);
                acc[e][3] = fmaf(tv.w, w3.w, acc[e][3]);
            }
        }
        float4 b2 = *(const float4*)&nb2[jj];
        #pragma unroll
        for (int e = 0; e < 4; e++) {
            int n = base + e0 + e;
            if (n < N) {
                float4 hv = *(const float4*)&h[(size_t)n * HD + jj];
                float4 o;
                o.x = hv.x + acc[e][0] + b2.x;
                o.y = hv.y + acc[e][1] + b2.y;
                o.z = hv.z + acc[e][2] + b2.z;
                o.w = hv.w + acc[e][3] + b2.w;
                *(float4*)&outH[(size_t)n * HD + jj] = o;
            }
        }
    }

    if (threadIdx.x < OTILE) {
        int n = base + threadIdx.x;
        if (n < N) {
            float c = fmaxf(g_cnt[n], 1.0f);
            outP[n * 3 + 0] = pos[n * 3 + 0] + g_psum[n * 3 + 0] / c;
            outP[n * 3 + 1] = pos[n * 3 + 1] + g_psum[n * 3 + 1] / c;
            outP[n * 3 + 2] = pos[n * 3 + 2] + g_psum[n * 3 + 2] / c;
        }
    }
}

// ---------------------------------------------------------------- launch
extern "C" void kernel_launch(void* const* d_in, const int* in_sizes, int n_in,
                              void* d_out, int out_size)
{
    const float* h    = (const float*)d_in[0];
    const float* pos  = (const float*)d_in[1];
    const int*   eidx = (const int*)d_in[2];
    const float* eW1  = (const float*)d_in[3];
    const float* eb1  = (const float*)d_in[4];
    const float* eW2  = (const float*)d_in[5];
    const float* eb2  = (const float*)d_in[6];
    const float* cW1  = (const float*)d_in[7];
    const float* cb1  = (const float*)d_in[8];
    const float* cW2  = (const float*)d_in[9];
    const float* nW1  = (const float*)d_in[10];
    const float* nb1  = (const float*)d_in[11];
    const float* nW2  = (const float*)d_in[12];
    const float* nb2  = (const float*)d_in[13];

    const int N = in_sizes[0] / HD;
    const int E = in_sizes[2] / 2;

    float* outH = (float*)d_out;
    float* outP = outH + (size_t)N * HD;

    zero_kernel<<<(N * (HD + 4) + 255) / 256, 256>>>(N);
    dup_weights_kernel<<<(HD * HD + 255) / 256, 256>>>(eW2, cW1);
    node_pre_kernel<<<(N + NTILE - 1) / NTILE, 256>>>(h, eW1, N);
    edge_kernel<<<(E + TILE - 1) / TILE, 256>>>(pos, eidx, eW1, eb1, eb2,
                                                cb1, cW2, N, E);
    node_out_kernel<<<(N + OTILE - 1) / OTILE, 256>>>(h, pos, nW1, nb1, nW2, nb2,
                                                      outH, outP, N);
}

// round 5
// speedup vs baseline: 1.6651x; 1.6651x over previous
#include <cuda_runtime.h>
#include <math.h>

#define HD 128
#define TILE 64      // edges per block tile (32 pairs)
#define NTILE 64     // nodes per block tile (pre)
#define OTILE 32     // nodes per block tile (out)
#define NMAX 20000
#define EMAX 640000

// Scratch (device globals: allocation-free)
__device__ float g_P[NMAX * HD];
__device__ float g_Q[NMAX * HD];
__device__ float g_mi[NMAX * HD];
__device__ float g_psum[NMAX * 3];
__device__ float g_cnt[NMAX];

__device__ __forceinline__ float silu(float x) {
    float hx = 0.5f * x;
    float t;
    asm("tanh.approx.f32 %0, %1;" : "=f"(t) : "f"(hx));
    return fmaf(hx, t, hx);          // 0.5x*(1+tanh(0.5x)) = x*sigmoid(x)
}

__device__ __forceinline__ void fma2(unsigned long long& acc,
                                     unsigned long long a, unsigned long long b) {
    asm("fma.rn.f32x2 %0, %1, %2, %0;" : "+l"(acc) : "l"(a), "l"(b));
}

// duplicate one float into both halves of an f32x2 register pair (alu-pipe mov)
__device__ __forceinline__ unsigned long long dup2(float x) {
    unsigned long long r;
    asm("mov.b64 %0, {%1, %1};" : "=l"(r) : "f"(x));
    return r;
}

__device__ __forceinline__ void lds_v2u64(unsigned long long& a, unsigned long long& b,
                                          unsigned addr) {
    asm volatile("ld.shared.v2.b64 {%0, %1}, [%2];" : "=l"(a), "=l"(b) : "r"(addr));
}

__device__ __forceinline__ unsigned smem_u32(const void* p) {
    unsigned r;
    asm("{ .reg .u64 t; cvta.to.shared.u64 t, %1; cvt.u32.u64 %0, t; }"
        : "=r"(r) : "l"(p));
    return r;
}

__device__ __forceinline__ float f2lo(unsigned long long v) {
    return __uint_as_float((unsigned)(v & 0xFFFFFFFFull));
}
__device__ __forceinline__ float f2hi(unsigned long long v) {
    return __uint_as_float((unsigned)(v >> 32));
}

// ---------------------------------------------------------------- zero
__global__ void zero_kernel(int N) {
    int i = blockIdx.x * blockDim.x + threadIdx.x;
    if (i < N * HD) g_mi[i] = 0.0f;
    int j = i - N * HD;
    if (j >= 0 && j < N * 3) g_psum[j] = 0.0f;
    int k = i - N * (HD + 3);
    if (k >= 0 && k < N) g_cnt[k] = 0.0f;
}

// ---------------------------------------------------------------- node pre:
// P = h @ eW1[0:128,:], Q = h @ eW1[128:256,:]
__global__ __launch_bounds__(256) void node_pre_kernel(
    const float* __restrict__ h, const float* __restrict__ eW1, int N)
{
    __shared__ float sH[NTILE * HD];   // 32 KB

    const int base = blockIdx.x * NTILE;

    for (int idx = threadIdx.x; idx < NTILE * HD; idx += 256) {
        int n = base + (idx >> 7);
        sH[idx] = (n < N) ? h[(size_t)n * HD + (idx & 127)] : 0.0f;
    }
    __syncthreads();

    const int lane = threadIdx.x & 31;
    const int warp = threadIdx.x >> 5;
    const int jj = lane * 4;
    const int e0 = warp * 8;

    #pragma unroll
    for (int half = 0; half < 2; half++) {
        const float* W = eW1 + (size_t)half * HD * HD;
        float* out = half ? g_Q : g_P;

        float acc[8][4];
        #pragma unroll
        for (int e = 0; e < 8; e++)
            #pragma unroll
            for (int i = 0; i < 4; i++) acc[e][i] = 0.f;

        for (int k = 0; k < HD; k += 4) {
            float4 w0 = *(const float4*)&W[(k + 0) * HD + jj];
            float4 w1 = *(const float4*)&W[(k + 1) * HD + jj];
            float4 w2 = *(const float4*)&W[(k + 2) * HD + jj];
            float4 w3 = *(const float4*)&W[(k + 3) * HD + jj];
            #pragma unroll
            for (int e = 0; e < 8; e++) {
                float4 tv = *(const float4*)&sH[(e0 + e) * HD + k];
                acc[e][0] = fmaf(tv.x, w0.x, acc[e][0]);
                acc[e][1] = fmaf(tv.x, w0.y, acc[e][1]);
                acc[e][2] = fmaf(tv.x, w0.z, acc[e][2]);
                acc[e][3] = fmaf(tv.x, w0.w, acc[e][3]);
                acc[e][0] = fmaf(tv.y, w1.x, acc[e][0]);
                acc[e][1] = fmaf(tv.y, w1.y, acc[e][1]);
                acc[e][2] = fmaf(tv.y, w1.z, acc[e][2]);
                acc[e][3] = fmaf(tv.y, w1.w, acc[e][3]);
                acc[e][0] = fmaf(tv.z, w2.x, acc[e][0]);
                acc[e][1] = fmaf(tv.z, w2.y, acc[e][1]);
                acc[e][2] = fmaf(tv.z, w2.z, acc[e][2]);
                acc[e][3] = fmaf(tv.z, w2.w, acc[e][3]);
                acc[e][0] = fmaf(tv.w, w3.x, acc[e][0]);
                acc[e][1] = fmaf(tv.w, w3.y, acc[e][1]);
                acc[e][2] = fmaf(tv.w, w3.z, acc[e][2]);
                acc[e][3] = fmaf(tv.w, w3.w, acc[e][3]);
            }
        }
        #pragma unroll
        for (int e = 0; e < 8; e++) {
            int n = base + e0 + e;
            if (n < N) {
                float4 o = make_float4(acc[e][0], acc[e][1], acc[e][2], acc[e][3]);
                *(float4*)&out[(size_t)n * HD + jj] = o;
            }
        }
    }
}

// ---------------------------------------------------------------- edge kernel (f32x2)
// Tp[pair][k] = (val_e0, val_e1) pair-packed; each warp owns 4 pairs (8 edges).
// Weights: plain LDG.128 (non-duplicated), register-duplicated via mov.b64.
__global__ __launch_bounds__(256) void edge_kernel(
    const float* __restrict__ pos,
    const int* __restrict__ eidx,
    const float* __restrict__ eW1, const float* __restrict__ eb1,
    const float* __restrict__ eW2, const float* __restrict__ eb2,
    const float* __restrict__ cW1, const float* __restrict__ cb1,
    const float* __restrict__ cW2,
    int N, int E)
{
    __shared__ float2 Tp[(TILE / 2) * HD];   // 32 KB, T then M in place
    __shared__ float sSq[TILE], sCw[TILE], sDx[TILE], sDy[TILE], sDz[TILE];
    __shared__ int   sR[TILE], sC[TILE];

    const int base = blockIdx.x * TILE;

    if (threadIdx.x < TILE) {
        int e = base + threadIdx.x;
        int r = 0, c = 0;
        float dx = 0.f, dy = 0.f, dz = 0.f, sq = 0.f;
        if (e < E) {
            r = eidx[e];
            c = eidx[E + e];
            dx = pos[r * 3 + 0] - pos[c * 3 + 0];
            dy = pos[r * 3 + 1] - pos[c * 3 + 1];
            dz = pos[r * 3 + 2] - pos[c * 3 + 2];
            sq = dx * dx + dy * dy + dz * dz;
        }
        sR[threadIdx.x] = r; sC[threadIdx.x] = c;
        sSq[threadIdx.x] = sq;
        sDx[threadIdx.x] = dx; sDy[threadIdx.x] = dy; sDz[threadIdx.x] = dz;
    }
    __syncthreads();

    // assembly: Tp[p][k] = (silu(x_{2p,k}), silu(x_{2p+1,k}))
    const float* w256 = eW1 + 256 * HD;
    for (int idx = threadIdx.x; idx < (TILE / 2) * HD; idx += 256) {
        int p = idx >> 7, k = idx & 127;
        int ea = 2 * p, eb = 2 * p + 1;
        float wk = w256[k], bk = eb1[k];
        float x0 = g_P[(size_t)sR[ea] * HD + k] + g_Q[(size_t)sC[ea] * HD + k]
                 + sSq[ea] * wk + bk;
        float x1 = g_P[(size_t)sR[eb] * HD + k] + g_Q[(size_t)sC[eb] * HD + k]
                 + sSq[eb] * wk + bk;
        Tp[idx] = make_float2(silu(x0), silu(x1));
    }
    __syncthreads();

    const int lane = threadIdx.x & 31;
    const int warp = threadIdx.x >> 5;
    const int jj = lane * 4;           // 4 output cols per lane
    const int p0 = warp * 4;           // 4 pairs (8 edges) per warp

    const unsigned tp0 = smem_u32(Tp) + (unsigned)(p0 * HD) * 8u;

    // ---------------- GEMV 1: M = silu(T @ eW2 + eb2), in place (pair-packed)
    {
        unsigned long long acc[4][4];
        #pragma unroll
        for (int p = 0; p < 4; p++)
            #pragma unroll
            for (int c = 0; c < 4; c++) acc[p][c] = 0ull;

        #pragma unroll 4
        for (int kk = 0; kk < HD; kk += 2) {
            float4 wA = __ldg((const float4*)&eW2[(kk + 0) * HD + jj]);
            float4 wB = __ldg((const float4*)&eW2[(kk + 1) * HD + jj]);
            unsigned long long wa0 = dup2(wA.x), wa1 = dup2(wA.y),
                               wa2 = dup2(wA.z), wa3 = dup2(wA.w);
            unsigned long long wb0 = dup2(wB.x), wb1 = dup2(wB.y),
                               wb2 = dup2(wB.z), wb3 = dup2(wB.w);
            #pragma unroll
            for (int p = 0; p < 4; p++) {
                unsigned long long t0, t1;
                lds_v2u64(t0, t1, tp0 + (unsigned)(p * HD + kk) * 8u);
                fma2(acc[p][0], t0, wa0);
                fma2(acc[p][1], t0, wa1);
                fma2(acc[p][2], t0, wa2);
                fma2(acc[p][3], t0, wa3);
                fma2(acc[p][0], t1, wb0);
                fma2(acc[p][1], t1, wb1);
                fma2(acc[p][2], t1, wb2);
                fma2(acc[p][3], t1, wb3);
            }
        }
        __syncwarp();   // all lanes finished reading T rows of this warp
        float4 b2 = *(const float4*)&eb2[jj];
        float bv[4] = { b2.x, b2.y, b2.z, b2.w };
        #pragma unroll
        for (int p = 0; p < 4; p++) {
            #pragma unroll
            for (int c = 0; c < 4; c++) {
                float m0 = silu(f2lo(acc[p][c]) + bv[c]);
                float m1 = silu(f2hi(acc[p][c]) + bv[c]);
                Tp[(p0 + p) * HD + jj + c] = make_float2(m0, m1);
            }
        }
    }
    __syncwarp();

    // ---------------- GEMV 2: cw = silu(M @ cW1 + cb1) . cW2
    {
        unsigned long long acc[4][4];
        #pragma unroll
        for (int p = 0; p < 4; p++)
            #pragma unroll
            for (int c = 0; c < 4; c++) acc[p][c] = 0ull;

        #pragma unroll 4
        for (int kk = 0; kk < HD; kk += 2) {
            float4 wA = __ldg((const float4*)&cW1[(kk + 0) * HD + jj]);
            float4 wB = __ldg((const float4*)&cW1[(kk + 1) * HD + jj]);
            unsigned long long wa0 = dup2(wA.x), wa1 = dup2(wA.y),
                               wa2 = dup2(wA.z), wa3 = dup2(wA.w);
            unsigned long long wb0 = dup2(wB.x), wb1 = dup2(wB.y),
                               wb2 = dup2(wB.z), wb3 = dup2(wB.w);
            #pragma unroll
            for (int p = 0; p < 4; p++) {
                unsigned long long t0, t1;
                lds_v2u64(t0, t1, tp0 + (unsigned)(p * HD + kk) * 8u);
                fma2(acc[p][0], t0, wa0);
                fma2(acc[p][1], t0, wa1);
                fma2(acc[p][2], t0, wa2);
                fma2(acc[p][3], t0, wa3);
                fma2(acc[p][0], t1, wb0);
                fma2(acc[p][1], t1, wb1);
                fma2(acc[p][2], t1, wb2);
                fma2(acc[p][3], t1, wb3);
            }
        }
        float4 cb  = *(const float4*)&cb1[jj];
        float4 cw2 = *(const float4*)&cW2[jj];
        float cbv[4]  = { cb.x, cb.y, cb.z, cb.w };
        float cw2v[4] = { cw2.x, cw2.y, cw2.z, cw2.w };
        #pragma unroll
        for (int p = 0; p < 4; p++) {
            float s0 = 0.f, s1 = 0.f;
            #pragma unroll
            for (int c = 0; c < 4; c++) {
                s0 += silu(f2lo(acc[p][c]) + cbv[c]) * cw2v[c];
                s1 += silu(f2hi(acc[p][c]) + cbv[c]) * cw2v[c];
            }
            #pragma unroll
            for (int off = 16; off > 0; off >>= 1) {
                s0 += __shfl_xor_sync(0xFFFFFFFFu, s0, off);
                s1 += __shfl_xor_sync(0xFFFFFFFFu, s1, off);
            }
            if (lane == 0) {
                sCw[2 * (p0 + p)]     = s0;
                sCw[2 * (p0 + p) + 1] = s1;
            }
        }
    }
    __syncthreads();

    // scatter messages (Tp now holds M, pair-packed)
    for (int idx = threadIdx.x; idx < (TILE / 2) * HD; idx += 256) {
        int p = idx >> 7, k = idx & 127;
        float2 mv = Tp[idx];
        int ea = 2 * p, eb = 2 * p + 1;
        if (base + ea < E) atomicAdd(&g_mi[(size_t)sR[ea] * HD + k], mv.x);
        if (base + eb < E) atomicAdd(&g_mi[(size_t)sR[eb] * HD + k], mv.y);
    }
    // scatter pos updates + counts
    if (threadIdx.x < TILE) {
        int e = threadIdx.x;
        if (base + e < E) {
            float inv = rsqrtf(sSq[e] + 1e-8f);
            float w = sCw[e] * inv;
            int r = sR[e];
            atomicAdd(&g_psum[r * 3 + 0], sDx[e] * w);
            atomicAdd(&g_psum[r * 3 + 1], sDy[e] * w);
            atomicAdd(&g_psum[r * 3 + 2], sDz[e] * w);
            atomicAdd(&g_cnt[r], 1.0f);
        }
    }
}

// ---------------------------------------------------------------- node out MLP + pos
__global__ __launch_bounds__(256) void node_out_kernel(
    const float* __restrict__ h, const float* __restrict__ pos,
    const float* __restrict__ nW1, const float* __restrict__ nb1,
    const float* __restrict__ nW2, const float* __restrict__ nb2,
    float* __restrict__ outH, float* __restrict__ outP, int N)
{
    __shared__ float sX[OTILE * 2 * HD];   // 32 KB

    const int base = blockIdx.x * OTILE;

    for (int idx = threadIdx.x; idx < OTILE * 2 * HD; idx += 256) {
        int n = base + (idx >> 8);
        int j = idx & 255;
        float v = 0.f;
        if (n < N)
            v = (j < HD) ? h[(size_t)n * HD + j] : g_mi[(size_t)n * HD + (j - HD)];
        sX[idx] = v;
    }
    __syncthreads();

    const int lane = threadIdx.x & 31;
    const int warp = threadIdx.x >> 5;
    const int jj = lane * 4;
    const int e0 = warp * 4;

    // GEMV 1: U = silu([h|m] @ nW1 + nb1), in-place into cols [0,128)
    {
        float acc[4][4];
        #pragma unroll
        for (int e = 0; e < 4; e++)
            #pragma unroll
            for (int i = 0; i < 4; i++) acc[e][i] = 0.f;

        for (int k = 0; k < 2 * HD; k += 4) {
            float4 w0 = *(const float4*)&nW1[(k + 0) * HD + jj];
            float4 w1 = *(const float4*)&nW1[(k + 1) * HD + jj];
            float4 w2 = *(const float4*)&nW1[(k + 2) * HD + jj];
            float4 w3 = *(const float4*)&nW1[(k + 3) * HD + jj];
            #pragma unroll
            for (int e = 0; e < 4; e++) {
                float4 tv = *(const float4*)&sX[(e0 + e) * 2 * HD + k];
                acc[e][0] = fmaf(tv.x, w0.x, acc[e][0]);
                acc[e][1] = fmaf(tv.x, w0.y, acc[e][1]);
                acc[e][2] = fmaf(tv.x, w0.z, acc[e][2]);
                acc[e][3] = fmaf(tv.x, w0.w, acc[e][3]);
                acc[e][0] = fmaf(tv.y, w1.x, acc[e][0]);
                acc[e][1] = fmaf(tv.y, w1.y, acc[e][1]);
                acc[e][2] = fmaf(tv.y, w1.z, acc[e][2]);
                acc[e][3] = fmaf(tv.y, w1.w, acc[e][3]);
                acc[e][0] = fmaf(tv.z, w2.x, acc[e][0]);
                acc[e][1] = fmaf(tv.z, w2.y, acc[e][1]);
                acc[e][2] = fmaf(tv.z, w2.z, acc[e][2]);
                acc[e][3] = fmaf(tv.z, w2.w, acc[e][3]);
                acc[e][0] = fmaf(tv.w, w3.x, acc[e][0]);
                acc[e][1] = fmaf(tv.w, w3.y, acc[e][1]);
                acc[e][2] = fmaf(tv.w, w3.z, acc[e][2]);
                acc[e][3] = fmaf(tv.w, w3.w, acc[e][3]);
            }
        }
        __syncwarp();
        float4 b1 = *(const float4*)&nb1[jj];
        #pragma unroll
        for (int e = 0; e < 4; e++) {
            float4 u;
            u.x = silu(acc[e][0] + b1.x);
            u.y = silu(acc[e][1] + b1.y);
            u.z = silu(acc[e][2] + b1.z);
            u.w = silu(acc[e][3] + b1.w);
            *(float4*)&sX[(e0 + e) * 2 * HD + jj] = u;
        }
    }
    __syncwarp();

    // GEMV 2: out = h + U @ nW2 + nb2
    {
        float acc[4][4];
        #pragma unroll
        for (int e = 0; e < 4; e++)
            #pragma unroll
            for (int i = 0; i < 4; i++) acc[e][i] = 0.f;

        for (int k = 0; k < HD; k += 4) {
            float4 w0 = *(const float4*)&nW2[(k + 0) * HD + jj];
            float4 w1 = *(const float4*)&nW2[(k + 1) * HD + jj];
            float4 w2 = *(const float4*)&nW2[(k + 2) * HD + jj];
            float4 w3 = *(const float4*)&nW2[(k + 3) * HD + jj];
            #pragma unroll
            for (int e = 0; e < 4; e++) {
                float4 tv = *(const float4*)&sX[(e0 + e) * 2 * HD + k];
                acc[e][0] = fmaf(tv.x, w0.x, acc[e][0]);
                acc[e][1] = fmaf(tv.x, w0.y, acc[e][1]);
                acc[e][2] = fmaf(tv.x, w0.z, acc[e][2]);
                acc[e][3] = fmaf(tv.x, w0.w, acc[e][3]);
                acc[e][0] = fmaf(tv.y, w1.x, acc[e][0]);
                acc[e][1] = fmaf(tv.y, w1.y, acc[e][1]);
                acc[e][2] = fmaf(tv.y, w1.z, acc[e][2]);
                acc[e][3] = fmaf(tv.y, w1.w, acc[e][3]);
                acc[e][0] = fmaf(tv.z, w2.x, acc[e][0]);
                acc[e][1] = fmaf(tv.z, w2.y, acc[e][1]);
                acc[e][2] = fmaf(tv.z, w2.z, acc[e][2]);
                acc[e][3] = fmaf(tv.z, w2.w, acc[e][3]);
                acc[e][0] = fmaf(tv.w, w3.x, acc[e][0]);
                acc[e][1] = fmaf(tv.w, w3.y, acc[e][1]);
                acc[e][2] = fmaf(tv.w, w3.z, acc[e][2]);
                acc[e][3] = fmaf(tv.w, w3.w, acc[e][3]);
            }
        }
        float4 b2 = *(const float4*)&nb2[jj];
        #pragma unroll
        for (int e = 0; e < 4; e++) {
            int n = base + e0 + e;
            if (n < N) {
                float4 hv = *(const float4*)&h[(size_t)n * HD + jj];
                float4 o;
                o.x = hv.x + acc[e][0] + b2.x;
                o.y = hv.y + acc[e][1] + b2.y;
                o.z = hv.z + acc[e][2] + b2.z;
                o.w = hv.w + acc[e][3] + b2.w;
                *(float4*)&outH[(size_t)n * HD + jj] = o;
            }
        }
    }

    if (threadIdx.x < OTILE) {
        int n = base + threadIdx.x;
        if (n < N) {
            float c = fmaxf(g_cnt[n], 1.0f);
            outP[n * 3 + 0] = pos[n * 3 + 0] + g_psum[n * 3 + 0] / c;
            outP[n * 3 + 1] = pos[n * 3 + 1] + g_psum[n * 3 + 1] / c;
            outP[n * 3 + 2] = pos[n * 3 + 2] + g_psum[n * 3 + 2] / c;
        }
    }
}

// ---------------------------------------------------------------- launch
extern "C" void kernel_launch(void* const* d_in, const int* in_sizes, int n_in,
                              void* d_out, int out_size)
{
    const float* h    = (const float*)d_in[0];
    const float* pos  = (const float*)d_in[1];
    const int*   eidx = (const int*)d_in[2];
    const float* eW1  = (const float*)d_in[3];
    const float* eb1  = (const float*)d_in[4];
    const float* eW2  = (const float*)d_in[5];
    const float* eb2  = (const float*)d_in[6];
    const float* cW1  = (const float*)d_in[7];
    const float* cb1  = (const float*)d_in[8];
    const float* cW2  = (const float*)d_in[9];
    const float* nW1  = (const float*)d_in[10];
    const float* nb1  = (const float*)d_in[11];
    const float* nW2  = (const float*)d_in[12];
    const float* nb2  = (const float*)d_in[13];

    const int N = in_sizes[0] / HD;
    const int E = in_sizes[2] / 2;

    float* outH = (float*)d_out;
    float* outP = outH + (size_t)N * HD;

    zero_kernel<<<(N * (HD + 4) + 255) / 256, 256>>>(N);
    node_pre_kernel<<<(N + NTILE - 1) / NTILE, 256>>>(h, eW1, N);
    edge_kernel<<<(E + TILE - 1) / TILE, 256>>>(pos, eidx, eW1, eb1, eW2, eb2,
                                                cW1, cb1, cW2, N, E);
    node_out_kernel<<<(N + OTILE - 1) / OTILE, 256>>>(h, pos, nW1, nb1, nW2, nb2,
                                                      outH, outP, N);
}

// round 6
// speedup vs baseline: 1.8392x; 1.1045x over previous
#include <cuda_runtime.h>
#include <math.h>

#define HD 128
#define TILE 64      // edges per block tile (32 pairs), 128 threads
#define NTILE 64     // nodes per block tile (pre)
#define NMAX 20000
#define EMAX 640000

// Scratch (device globals: allocation-free)
__device__ float g_P[NMAX * HD];
__device__ float g_Q[NMAX * HD];
__device__ float g_mi[NMAX * HD];
__device__ float g_psum[NMAX * 3];
__device__ float g_cnt[NMAX];

__device__ __forceinline__ float silu(float x) {
    float hx = 0.5f * x;
    float t;
    asm("tanh.approx.f32 %0, %1;" : "=f"(t) : "f"(hx));
    return fmaf(hx, t, hx);
}

__device__ __forceinline__ void fma2(unsigned long long& acc,
                                     unsigned long long a, unsigned long long b) {
    asm("fma.rn.f32x2 %0, %1, %2, %0;" : "+l"(acc) : "l"(a), "l"(b));
}

__device__ __forceinline__ unsigned long long dup2(float x) {
    unsigned long long r;
    asm("mov.b64 %0, {%1, %1};" : "=l"(r) : "f"(x));
    return r;
}

__device__ __forceinline__ void lds_v2u64(unsigned long long& a, unsigned long long& b,
                                          unsigned addr) {
    asm volatile("ld.shared.v2.b64 {%0, %1}, [%2];" : "=l"(a), "=l"(b) : "r"(addr));
}

__device__ __forceinline__ unsigned smem_u32(const void* p) {
    unsigned r;
    asm("{ .reg .u64 t; cvta.to.shared.u64 t, %1; cvt.u32.u64 %0, t; }"
        : "=r"(r) : "l"(p));
    return r;
}

__device__ __forceinline__ float f2lo(unsigned long long v) {
    return __uint_as_float((unsigned)(v & 0xFFFFFFFFull));
}
__device__ __forceinline__ float f2hi(unsigned long long v) {
    return __uint_as_float((unsigned)(v >> 32));
}

// vector reduction: g_mi[addr..addr+1] += {a, b}   (sm_90+)
__device__ __forceinline__ void red_add_v2(float* p, float a, float b) {
    asm volatile("red.global.add.v2.f32 [%0], {%1, %2};"
                 :: "l"(p), "f"(a), "f"(b) : "memory");
}

// ---------------------------------------------------------------- zero
__global__ void zero_kernel(int N) {
    int i = blockIdx.x * blockDim.x + threadIdx.x;
    if (i < N * HD) g_mi[i] = 0.0f;
    int j = i - N * HD;
    if (j >= 0 && j < N * 3) g_psum[j] = 0.0f;
    int k = i - N * (HD + 3);
    if (k >= 0 && k < N) g_cnt[k] = 0.0f;
}

// ---------------------------------------------------------------- node pre (unchanged)
__global__ __launch_bounds__(256) void node_pre_kernel(
    const float* __restrict__ h, const float* __restrict__ eW1, int N)
{
    __shared__ float sH[NTILE * HD];

    const int base = blockIdx.x * NTILE;

    for (int idx = threadIdx.x; idx < NTILE * HD; idx += 256) {
        int n = base + (idx >> 7);
        sH[idx] = (n < N) ? h[(size_t)n * HD + (idx & 127)] : 0.0f;
    }
    __syncthreads();

    const int lane = threadIdx.x & 31;
    const int warp = threadIdx.x >> 5;
    const int jj = lane * 4;
    const int e0 = warp * 8;

    #pragma unroll
    for (int half = 0; half < 2; half++) {
        const float* W = eW1 + (size_t)half * HD * HD;
        float* out = half ? g_Q : g_P;

        float acc[8][4];
        #pragma unroll
        for (int e = 0; e < 8; e++)
            #pragma unroll
            for (int i = 0; i < 4; i++) acc[e][i] = 0.f;

        for (int k = 0; k < HD; k += 4) {
            float4 w0 = *(const float4*)&W[(k + 0) * HD + jj];
            float4 w1 = *(const float4*)&W[(k + 1) * HD + jj];
            float4 w2 = *(const float4*)&W[(k + 2) * HD + jj];
            float4 w3 = *(const float4*)&W[(k + 3) * HD + jj];
            #pragma unroll
            for (int e = 0; e < 8; e++) {
                float4 tv = *(const float4*)&sH[(e0 + e) * HD + k];
                acc[e][0] = fmaf(tv.x, w0.x, acc[e][0]);
                acc[e][1] = fmaf(tv.x, w0.y, acc[e][1]);
                acc[e][2] = fmaf(tv.x, w0.z, acc[e][2]);
                acc[e][3] = fmaf(tv.x, w0.w, acc[e][3]);
                acc[e][0] = fmaf(tv.y, w1.x, acc[e][0]);
                acc[e][1] = fmaf(tv.y, w1.y, acc[e][1]);
                acc[e][2] = fmaf(tv.y, w1.z, acc[e][2]);
                acc[e][3] = fmaf(tv.y, w1.w, acc[e][3]);
                acc[e][0] = fmaf(tv.z, w2.x, acc[e][0]);
                acc[e][1] = fmaf(tv.z, w2.y, acc[e][1]);
                acc[e][2] = fmaf(tv.z, w2.z, acc[e][2]);
                acc[e][3] = fmaf(tv.z, w2.w, acc[e][3]);
                acc[e][0] = fmaf(tv.w, w3.x, acc[e][0]);
                acc[e][1] = fmaf(tv.w, w3.y, acc[e][1]);
                acc[e][2] = fmaf(tv.w, w3.z, acc[e][2]);
                acc[e][3] = fmaf(tv.w, w3.w, acc[e][3]);
            }
        }
        #pragma unroll
        for (int e = 0; e < 8; e++) {
            int n = base + e0 + e;
            if (n < N) {
                float4 o = make_float4(acc[e][0], acc[e][1], acc[e][2], acc[e][3]);
                *(float4*)&out[(size_t)n * HD + jj] = o;
            }
        }
    }
}

// ---------------------------------------------------------------- edge kernel
// 128 threads, 64 edges (32 pairs), 4 warps x 8 pairs. E % 64 == 0.
__global__ __launch_bounds__(128) void edge_kernel(
    const float* __restrict__ pos,
    const int* __restrict__ eidx,
    const float* __restrict__ eW1, const float* __restrict__ eb1,
    const float* __restrict__ eW2, const float* __restrict__ eb2,
    const float* __restrict__ cW1, const float* __restrict__ cb1,
    const float* __restrict__ cW2,
    int N, int E)
{
    __shared__ __align__(16) float2 Tp[(TILE / 2) * HD];   // 32 KB
    __shared__ float sSq[TILE], sCw[TILE], sDx[TILE], sDy[TILE], sDz[TILE];
    __shared__ int   sR[TILE], sC[TILE];

    const int base = blockIdx.x * TILE;
    const int tid = threadIdx.x;

    if (tid < TILE) {
        int e = base + tid;
        int r = eidx[e];
        int c = eidx[E + e];
        float dx = pos[r * 3 + 0] - pos[c * 3 + 0];
        float dy = pos[r * 3 + 1] - pos[c * 3 + 1];
        float dz = pos[r * 3 + 2] - pos[c * 3 + 2];
        float sq = dx * dx + dy * dy + dz * dz;
        sR[tid] = r; sC[tid] = c;
        sSq[tid] = sq;
        sDx[tid] = dx; sDy[tid] = dy; sDz[tid] = dz;
    }
    __syncthreads();

    // assembly (float4 gather): Tp[p][k] = (silu(x_e0_k), silu(x_e1_k))
    const float* w256 = eW1 + 256 * HD;
    for (int idx = tid; idx < (TILE / 2) * (HD / 4); idx += 128) {
        int p = idx >> 5, kg = idx & 31, k = kg << 2;
        int ea = 2 * p, eb = 2 * p + 1;
        float sq0 = sSq[ea], sq1 = sSq[eb];
        float4 P0 = __ldg((const float4*)&g_P[(size_t)sR[ea] * HD + k]);
        float4 Q0 = __ldg((const float4*)&g_Q[(size_t)sC[ea] * HD + k]);
        float4 P1 = __ldg((const float4*)&g_P[(size_t)sR[eb] * HD + k]);
        float4 Q1 = __ldg((const float4*)&g_Q[(size_t)sC[eb] * HD + k]);
        float4 wv = __ldg((const float4*)&w256[k]);
        float4 bv = __ldg((const float4*)&eb1[k]);
        float s00 = silu(P0.x + Q0.x + sq0 * wv.x + bv.x);
        float s01 = silu(P0.y + Q0.y + sq0 * wv.y + bv.y);
        float s02 = silu(P0.z + Q0.z + sq0 * wv.z + bv.z);
        float s03 = silu(P0.w + Q0.w + sq0 * wv.w + bv.w);
        float s10 = silu(P1.x + Q1.x + sq1 * wv.x + bv.x);
        float s11 = silu(P1.y + Q1.y + sq1 * wv.y + bv.y);
        float s12 = silu(P1.z + Q1.z + sq1 * wv.z + bv.z);
        float s13 = silu(P1.w + Q1.w + sq1 * wv.w + bv.w);
        *(float4*)&Tp[p * HD + k]     = make_float4(s00, s10, s01, s11);
        *(float4*)&Tp[p * HD + k + 2] = make_float4(s02, s12, s03, s13);
    }
    __syncthreads();

    const int lane = tid & 31;
    const int warp = tid >> 5;          // 0..3
    const int jj = lane * 4;            // 4 output cols per lane
    const int p0 = warp * 8;            // 8 pairs (16 edges) per warp

    const unsigned tp0 = smem_u32(Tp) + (unsigned)(p0 * HD) * 8u;

    // ---------------- GEMV 1: M = silu(T @ eW2 + eb2), in place
    {
        unsigned long long acc[8][4];
        #pragma unroll
        for (int p = 0; p < 8; p++)
            #pragma unroll
            for (int c = 0; c < 4; c++) acc[p][c] = 0ull;

        #pragma unroll 2
        for (int kk = 0; kk < HD; kk += 2) {
            float4 wA = __ldg((const float4*)&eW2[(kk + 0) * HD + jj]);
            float4 wB = __ldg((const float4*)&eW2[(kk + 1) * HD + jj]);
            unsigned long long wa0 = dup2(wA.x), wa1 = dup2(wA.y),
                               wa2 = dup2(wA.z), wa3 = dup2(wA.w);
            unsigned long long wb0 = dup2(wB.x), wb1 = dup2(wB.y),
                               wb2 = dup2(wB.z), wb3 = dup2(wB.w);
            #pragma unroll
            for (int p = 0; p < 8; p++) {
                unsigned long long t0, t1;
                lds_v2u64(t0, t1, tp0 + (unsigned)(p * HD + kk) * 8u);
                fma2(acc[p][0], t0, wa0);
                fma2(acc[p][1], t0, wa1);
                fma2(acc[p][2], t0, wa2);
                fma2(acc[p][3], t0, wa3);
                fma2(acc[p][0], t1, wb0);
                fma2(acc[p][1], t1, wb1);
                fma2(acc[p][2], t1, wb2);
                fma2(acc[p][3], t1, wb3);
            }
        }
        __syncwarp();
        float4 b2 = *(const float4*)&eb2[jj];
        float bv[4] = { b2.x, b2.y, b2.z, b2.w };
        #pragma unroll
        for (int p = 0; p < 8; p++) {
            float4 A = make_float4(silu(f2lo(acc[p][0]) + bv[0]),
                                   silu(f2hi(acc[p][0]) + bv[0]),
                                   silu(f2lo(acc[p][1]) + bv[1]),
                                   silu(f2hi(acc[p][1]) + bv[1]));
            float4 B = make_float4(silu(f2lo(acc[p][2]) + bv[2]),
                                   silu(f2hi(acc[p][2]) + bv[2]),
                                   silu(f2lo(acc[p][3]) + bv[3]),
                                   silu(f2hi(acc[p][3]) + bv[3]));
            *(float4*)&Tp[(p0 + p) * HD + jj]     = A;
            *(float4*)&Tp[(p0 + p) * HD + jj + 2] = B;
        }
    }
    __syncwarp();

    // ---------------- GEMV 2: cw = silu(M @ cW1 + cb1) . cW2
    {
        unsigned long long acc[8][4];
        #pragma unroll
        for (int p = 0; p < 8; p++)
            #pragma unroll
            for (int c = 0; c < 4; c++) acc[p][c] = 0ull;

        #pragma unroll 2
        for (int kk = 0; kk < HD; kk += 2) {
            float4 wA = __ldg((const float4*)&cW1[(kk + 0) * HD + jj]);
            float4 wB = __ldg((const float4*)&cW1[(kk + 1) * HD + jj]);
            unsigned long long wa0 = dup2(wA.x), wa1 = dup2(wA.y),
                               wa2 = dup2(wA.z), wa3 = dup2(wA.w);
            unsigned long long wb0 = dup2(wB.x), wb1 = dup2(wB.y),
                               wb2 = dup2(wB.z), wb3 = dup2(wB.w);
            #pragma unroll
            for (int p = 0; p < 8; p++) {
                unsigned long long t0, t1;
                lds_v2u64(t0, t1, tp0 + (unsigned)(p * HD + kk) * 8u);
                fma2(acc[p][0], t0, wa0);
                fma2(acc[p][1], t0, wa1);
                fma2(acc[p][2], t0, wa2);
                fma2(acc[p][3], t0, wa3);
                fma2(acc[p][0], t1, wb0);
                fma2(acc[p][1], t1, wb1);
                fma2(acc[p][2], t1, wb2);
                fma2(acc[p][3], t1, wb3);
            }
        }
        float4 cb  = *(const float4*)&cb1[jj];
        float4 cw2 = *(const float4*)&cW2[jj];
        float cbv[4]  = { cb.x, cb.y, cb.z, cb.w };
        float cw2v[4] = { cw2.x, cw2.y, cw2.z, cw2.w };
        #pragma unroll
        for (int p = 0; p < 8; p++) {
            float s0 = 0.f, s1 = 0.f;
            #pragma unroll
            for (int c = 0; c < 4; c++) {
                s0 += silu(f2lo(acc[p][c]) + cbv[c]) * cw2v[c];
                s1 += silu(f2hi(acc[p][c]) + cbv[c]) * cw2v[c];
            }
            #pragma unroll
            for (int off = 16; off > 0; off >>= 1) {
                s0 += __shfl_xor_sync(0xFFFFFFFFu, s0, off);
                s1 += __shfl_xor_sync(0xFFFFFFFFu, s1, off);
            }
            if (lane == 0) {
                sCw[2 * (p0 + p)]     = s0;
                sCw[2 * (p0 + p) + 1] = s1;
            }
        }
    }
    __syncthreads();

    // scatter messages with vector reductions (Tp holds M, pair-packed)
    for (int idx = tid; idx < (TILE / 2) * (HD / 2); idx += 128) {
        int p = idx >> 6, kp = idx & 63, k = kp << 1;
        float4 v = *(const float4*)&Tp[p * HD + k];  // (e0_k, e1_k, e0_k1, e1_k1)
        int r0 = sR[2 * p], r1 = sR[2 * p + 1];
        red_add_v2(&g_mi[(size_t)r0 * HD + k], v.x, v.z);
        red_add_v2(&g_mi[(size_t)r1 * HD + k], v.y, v.w);
    }
    // scatter pos updates + counts
    if (tid < TILE) {
        float inv = rsqrtf(sSq[tid] + 1e-8f);
        float w = sCw[tid] * inv;
        int r = sR[tid];
        atomicAdd(&g_psum[r * 3 + 0], sDx[tid] * w);
        atomicAdd(&g_psum[r * 3 + 1], sDy[tid] * w);
        atomicAdd(&g_psum[r * 3 + 2], sDz[tid] * w);
        atomicAdd(&g_cnt[r], 1.0f);
    }
}

// ---------------------------------------------------------------- node out (f32x2)
// 128 threads, 32 nodes (16 pairs), 4 warps x 4 pairs. N % 32 == 0.
__global__ __launch_bounds__(128) void node_out_kernel(
    const float* __restrict__ h, const float* __restrict__ pos,
    const float* __restrict__ nW1, const float* __restrict__ nb1,
    const float* __restrict__ nW2, const float* __restrict__ nb2,
    float* __restrict__ outH, float* __restrict__ outP, int N)
{
    __shared__ __align__(16) float2 sXp[16 * 2 * HD];   // 32 KB, pair-packed

    const int base = blockIdx.x * 32;
    const int tid = threadIdx.x;

    // stage [h | m_i] pair-packed
    for (int idx = tid; idx < 16 * (2 * HD / 4); idx += 128) {
        int p = idx >> 6, kg = idx & 63, k = kg << 2;
        int n0 = base + 2 * p, n1 = n0 + 1;
        float4 a, b;
        if (k < HD) {
            a = __ldg((const float4*)&h[(size_t)n0 * HD + k]);
            b = __ldg((const float4*)&h[(size_t)n1 * HD + k]);
        } else {
            a = *(const float4*)&g_mi[(size_t)n0 * HD + (k - HD)];
            b = *(const float4*)&g_mi[(size_t)n1 * HD + (k - HD)];
        }
        *(float4*)&sXp[p * 2 * HD + k]     = make_float4(a.x, b.x, a.y, b.y);
        *(float4*)&sXp[p * 2 * HD + k + 2] = make_float4(a.z, b.z, a.w, b.w);
    }
    __syncthreads();

    const int lane = tid & 31;
    const int warp = tid >> 5;
    const int jj = lane * 4;
    const int p0 = warp * 4;          // 4 pairs (8 nodes) per warp

    const unsigned x0 = smem_u32(sXp) + (unsigned)(p0 * 2 * HD) * 8u;

    // GEMV 1: U = silu([h|m] @ nW1 + nb1), in-place into cols [0,128)
    {
        unsigned long long acc[4][4];
        #pragma unroll
        for (int p = 0; p < 4; p++)
            #pragma unroll
            for (int c = 0; c < 4; c++) acc[p][c] = 0ull;

        #pragma unroll 2
        for (int kk = 0; kk < 2 * HD; kk += 2) {
            float4 wA = __ldg((const float4*)&nW1[(kk + 0) * HD + jj]);
            float4 wB = __ldg((const float4*)&nW1[(kk + 1) * HD + jj]);
            unsigned long long wa0 = dup2(wA.x), wa1 = dup2(wA.y),
                               wa2 = dup2(wA.z), wa3 = dup2(wA.w);
            unsigned long long wb0 = dup2(wB.x), wb1 = dup2(wB.y),
                               wb2 = dup2(wB.z), wb3 = dup2(wB.w);
            #pragma unroll
            for (int p = 0; p < 4; p++) {
                unsigned long long t0, t1;
                lds_v2u64(t0, t1, x0 + (unsigned)(p * 2 * HD + kk) * 8u);
                fma2(acc[p][0], t0, wa0);
                fma2(acc[p][1], t0, wa1);
                fma2(acc[p][2], t0, wa2);
                fma2(acc[p][3], t0, wa3);
                fma2(acc[p][0], t1, wb0);
                fma2(acc[p][1], t1, wb1);
                fma2(acc[p][2], t1, wb2);
                fma2(acc[p][3], t1, wb3);
            }
        }
        __syncwarp();
        float4 b1 = *(const float4*)&nb1[jj];
        float bv[4] = { b1.x, b1.y, b1.z, b1.w };
        #pragma unroll
        for (int p = 0; p < 4; p++) {
            float4 A = make_float4(silu(f2lo(acc[p][0]) + bv[0]),
                                   silu(f2hi(acc[p][0]) + bv[0]),
                                   silu(f2lo(acc[p][1]) + bv[1]),
                                   silu(f2hi(acc[p][1]) + bv[1]));
            float4 B = make_float4(silu(f2lo(acc[p][2]) + bv[2]),
                                   silu(f2hi(acc[p][2]) + bv[2]),
                                   silu(f2lo(acc[p][3]) + bv[3]),
                                   silu(f2hi(acc[p][3]) + bv[3]));
            *(float4*)&sXp[(p0 + p) * 2 * HD + jj]     = A;
            *(float4*)&sXp[(p0 + p) * 2 * HD + jj + 2] = B;
        }
    }
    __syncwarp();

    // GEMV 2: out = h + U @ nW2 + nb2
    {
        unsigned long long acc[4][4];
        #pragma unroll
        for (int p = 0; p < 4; p++)
            #pragma unroll
            for (int c = 0; c < 4; c++) acc[p][c] = 0ull;

        #pragma unroll 2
        for (int kk = 0; kk < HD; kk += 2) {
            float4 wA = __ldg((const float4*)&nW2[(kk + 0) * HD + jj]);
            float4 wB = __ldg((const float4*)&nW2[(kk + 1) * HD + jj]);
            unsigned long long wa0 = dup2(wA.x), wa1 = dup2(wA.y),
                               wa2 = dup2(wA.z), wa3 = dup2(wA.w);
            unsigned long long wb0 = dup2(wB.x), wb1 = dup2(wB.y),
                               wb2 = dup2(wB.z), wb3 = dup2(wB.w);
            #pragma unroll
            for (int p = 0; p < 4; p++) {
                unsigned long long t0, t1;
                lds_v2u64(t0, t1, x0 + (unsigned)(p * 2 * HD + kk) * 8u);
                fma2(acc[p][0], t0, wa0);
                fma2(acc[p][1], t0, wa1);
                fma2(acc[p][2], t0, wa2);
                fma2(acc[p][3], t0, wa3);
                fma2(acc[p][0], t1, wb0);
                fma2(acc[p][1], t1, wb1);
                fma2(acc[p][2], t1, wb2);
                fma2(acc[p][3], t1, wb3);
            }
        }
        float4 b2 = *(const float4*)&nb2[jj];
        #pragma unroll
        for (int p = 0; p < 4; p++) {
            int n0 = base + 2 * (p0 + p), n1 = n0 + 1;
            float4 h0 = __ldg((const float4*)&h[(size_t)n0 * HD + jj]);
            float4 h1 = __ldg((const float4*)&h[(size_t)n1 * HD + jj]);
            float4 o0 = make_float4(h0.x + f2lo(acc[p][0]) + b2.x,
                                    h0.y + f2lo(acc[p][1]) + b2.y,
                                    h0.z + f2lo(acc[p][2]) + b2.z,
                                    h0.w + f2lo(acc[p][3]) + b2.w);
            float4 o1 = make_float4(h1.x + f2hi(acc[p][0]) + b2.x,
                                    h1.y + f2hi(acc[p][1]) + b2.y,
                                    h1.z + f2hi(acc[p][2]) + b2.z,
                                    h1.w + f2hi(acc[p][3]) + b2.w);
            *(float4*)&outH[(size_t)n0 * HD + jj] = o0;
            *(float4*)&outH[(size_t)n1 * HD + jj] = o1;
        }
    }

    if (tid < 32) {
        int n = base + tid;
        float c = fmaxf(g_cnt[n], 1.0f);
        outP[n * 3 + 0] = pos[n * 3 + 0] + g_psum[n * 3 + 0] / c;
        outP[n * 3 + 1] = pos[n * 3 + 1] + g_psum[n * 3 + 1] / c;
        outP[n * 3 + 2] = pos[n * 3 + 2] + g_psum[n * 3 + 2] / c;
    }
}

// ---------------------------------------------------------------- launch
extern "C" void kernel_launch(void* const* d_in, const int* in_sizes, int n_in,
                              void* d_out, int out_size)
{
    const float* h    = (const float*)d_in[0];
    const float* pos  = (const float*)d_in[1];
    const int*   eidx = (const int*)d_in[2];
    const float* eW1  = (const float*)d_in[3];
    const float* eb1  = (const float*)d_in[4];
    const float* eW2  = (const float*)d_in[5];
    const float* eb2  = (const float*)d_in[6];
    const float* cW1  = (const float*)d_in[7];
    const float* cb1  = (const float*)d_in[8];
    const float* cW2  = (const float*)d_in[9];
    const float* nW1  = (const float*)d_in[10];
    const float* nb1  = (const float*)d_in[11];
    const float* nW2  = (const float*)d_in[12];
    const float* nb2  = (const float*)d_in[13];

    const int N = in_sizes[0] / HD;
    const int E = in_sizes[2] / 2;

    float* outH = (float*)d_out;
    float* outP = outH + (size_t)N * HD;

    zero_kernel<<<(N * (HD + 4) + 255) / 256, 256>>>(N);
    node_pre_kernel<<<(N + NTILE - 1) / NTILE, 256>>>(h, eW1, N);
    edge_kernel<<<(E + TILE - 1) / TILE, 128>>>(pos, eidx, eW1, eb1, eW2, eb2,
                                                cW1, cb1, cW2, N, E);
    node_out_kernel<<<N / 32, 128>>>(h, pos, nW1, nb1, nW2, nb2, outH, outP, N);
}

// round 9
// speedup vs baseline: 2.5312x; 1.3763x over previous
#include <cuda_runtime.h>
#include <cuda_bf16.h>
#include <math.h>

#define HD 128
#define ETILE 128
#define NTILE 64
#define NMAX 20000
#define EMAX 640000

// ---------------- scratch (device globals: allocation-free)
__device__ float g_P[NMAX * HD];
__device__ float g_Q[NMAX * HD];
__device__ float g_mi[NMAX * HD];
__device__ float g_psum[NMAX * 3];
__device__ float g_cnt[NMAX];
// fragment-packed transposed weight images
__device__ __align__(16) unsigned char g_imgW2[65536];  // eW2^T bf16 hi(0)/lo(32768)
__device__ __align__(16) unsigned char g_imgC1[32768];  // cW1^T bf16 hi only

// ---------------- helpers
__device__ __forceinline__ float silu(float x) {
    float hx = 0.5f * x;
    float t;
    asm("tanh.approx.f32 %0, %1;" : "=f"(t) : "f"(hx));
    return fmaf(hx, t, hx);
}

__device__ __forceinline__ unsigned smem_u32(const void* p) {
    unsigned r;
    asm("{ .reg .u64 t; cvta.to.shared.u64 t, %1; cvt.u32.u64 %0, t; }"
        : "=r"(r) : "l"(p));
    return r;
}

__device__ __forceinline__ void red_add_v2(float* p, float a, float b) {
    asm volatile("red.global.add.v2.f32 [%0], {%1, %2};"
                 :: "l"(p), "f"(a), "f"(b) : "memory");
}

__device__ __forceinline__ unsigned bfpack(__nv_bfloat16 a, __nv_bfloat16 b) {
    unsigned short ua = __bfloat16_as_ushort(a), ub = __bfloat16_as_ushort(b);
    return (unsigned)ua | ((unsigned)ub << 16);
}

__device__ __forceinline__ void bfsplit(float v, __nv_bfloat16& hi, __nv_bfloat16& lo) {
    hi = __float2bfloat16(v);
    lo = __float2bfloat16(v - __bfloat162float(hi));
}

// m16n8k16 row.col f32.bf16.bf16.f32 — standard PTX, valid on base sm_103
__device__ __forceinline__ void mma_bf16(float* c, const uint4& a, const uint2& b) {
    asm volatile(
        "mma.sync.aligned.m16n8k16.row.col.f32.bf16.bf16.f32 "
        "{%0,%1,%2,%3}, {%4,%5,%6,%7}, {%8,%9}, {%0,%1,%2,%3};"
        : "+f"(c[0]), "+f"(c[1]), "+f"(c[2]), "+f"(c[3])
        : "r"(a.x), "r"(a.y), "r"(a.z), "r"(a.w), "r"(b.x), "r"(b.y));
}

// SMEM layout offsets
#define SM_A     0        // A image: hi @0, lo @32768 (64 KB)
#define SM_W2    65536    // W2t image hi @0, lo @32768 (64 KB)
#define SM_C1    131072   // C1t image hi (32 KB)
#define SM_META  163840
#define EDGE_SMEM 167936

// ---------------------------------------------------------------- zero
__global__ void zero_kernel(int N) {
    int i = blockIdx.x * blockDim.x + threadIdx.x;
    if (i < N * HD) g_mi[i] = 0.0f;
    int j = i - N * HD;
    if (j >= 0 && j < N * 3) g_psum[j] = 0.0f;
    int k = i - N * (HD + 3);
    if (k >= 0 && k < N) g_cnt[k] = 0.0f;
}

// ---------------------------------------------------------------- weight prep
// B[n][k] = W[k][n], packed into m16n8k16 B-fragment slots:
//   natom=n>>3, kstep=k>>4, lane=(n&7)*4+((k&7)>>1), reg=(k&15)>>3, half=k&1
//   byte = ((natom*8+kstep)*32 + lane)*8 + reg*4 + half*2
__global__ void prep_weights_kernel(const float* __restrict__ eW2,
                                    const float* __restrict__ cW1) {
    int i = blockIdx.x * blockDim.x + threadIdx.x;
    if (i >= HD * HD) return;
    int k = i >> 7, n = i & 127;
    unsigned off = (((unsigned)(n >> 3) * 8u + (unsigned)(k >> 4)) * 32u
                    + (unsigned)((n & 7) * 4 + ((k & 7) >> 1))) * 8u
                 + (unsigned)(((k & 15) >> 3) * 4) + (unsigned)((k & 1) * 2);
    __nv_bfloat16 hi, lo;
    bfsplit(eW2[i], hi, lo);
    *(__nv_bfloat16*)(g_imgW2 + off) = hi;
    *(__nv_bfloat16*)(g_imgW2 + 32768 + off) = lo;
    *(__nv_bfloat16*)(g_imgC1 + off) = __float2bfloat16(cW1[i]);
}

// ---------------------------------------------------------------- node pre (R6)
__global__ __launch_bounds__(256) void node_pre_kernel(
    const float* __restrict__ h, const float* __restrict__ eW1, int N)
{
    __shared__ float sH[NTILE * HD];
    const int base = blockIdx.x * NTILE;

    for (int idx = threadIdx.x; idx < NTILE * HD; idx += 256) {
        int n = base + (idx >> 7);
        sH[idx] = (n < N) ? h[(size_t)n * HD + (idx & 127)] : 0.0f;
    }
    __syncthreads();

    const int lane = threadIdx.x & 31;
    const int warp = threadIdx.x >> 5;
    const int jj = lane * 4;
    const int e0 = warp * 8;

    #pragma unroll
    for (int half = 0; half < 2; half++) {
        const float* W = eW1 + (size_t)half * HD * HD;
        float* out = half ? g_Q : g_P;

        float acc[8][4];
        #pragma unroll
        for (int e = 0; e < 8; e++)
            #pragma unroll
            for (int i = 0; i < 4; i++) acc[e][i] = 0.f;

        for (int k = 0; k < HD; k += 4) {
            float4 w0 = *(const float4*)&W[(k + 0) * HD + jj];
            float4 w1 = *(const float4*)&W[(k + 1) * HD + jj];
            float4 w2 = *(const float4*)&W[(k + 2) * HD + jj];
            float4 w3 = *(const float4*)&W[(k + 3) * HD + jj];
            #pragma unroll
            for (int e = 0; e < 8; e++) {
                float4 tv = *(const float4*)&sH[(e0 + e) * HD + k];
                acc[e][0] = fmaf(tv.x, w0.x, acc[e][0]);
                acc[e][1] = fmaf(tv.x, w0.y, acc[e][1]);
                acc[e][2] = fmaf(tv.x, w0.z, acc[e][2]);
                acc[e][3] = fmaf(tv.x, w0.w, acc[e][3]);
                acc[e][0] = fmaf(tv.y, w1.x, acc[e][0]);
                acc[e][1] = fmaf(tv.y, w1.y, acc[e][1]);
                acc[e][2] = fmaf(tv.y, w1.z, acc[e][2]);
                acc[e][3] = fmaf(tv.y, w1.w, acc[e][3]);
                acc[e][0] = fmaf(tv.z, w2.x, acc[e][0]);
                acc[e][1] = fmaf(tv.z, w2.y, acc[e][1]);
                acc[e][2] = fmaf(tv.z, w2.z, acc[e][2]);
                acc[e][3] = fmaf(tv.z, w2.w, acc[e][3]);
                acc[e][0] = fmaf(tv.w, w3.x, acc[e][0]);
                acc[e][1] = fmaf(tv.w, w3.y, acc[e][1]);
                acc[e][2] = fmaf(tv.w, w3.z, acc[e][2]);
                acc[e][3] = fmaf(tv.w, w3.w, acc[e][3]);
            }
        }
        #pragma unroll
        for (int e = 0; e < 8; e++) {
            int n = base + e0 + e;
            if (n < N) {
                float4 o = make_float4(acc[e][0], acc[e][1], acc[e][2], acc[e][3]);
                *(float4*)&out[(size_t)n * HD + jj] = o;
            }
        }
    }
}

// ---------------------------------------------------------------- edge kernel (mma.sync bf16)
// Persistent, 256 threads (8 warps), 128-edge tiles.
// Warp w: output rows [(w&3)*32, +32), cols [(w>>2)*64, +64).
__global__ __launch_bounds__(256, 1) void edge_kernel(
    const float* __restrict__ pos,
    const int* __restrict__ eidx,
    const float* __restrict__ eW1, const float* __restrict__ eb1,
    const float* __restrict__ eb2,
    const float* __restrict__ cb1, const float* __restrict__ cW2,
    int N, int E, int numTiles)
{
    extern __shared__ __align__(16) unsigned char S[];

    const int tid  = threadIdx.x;
    const int w    = tid >> 5;
    const int lane = tid & 31;

    int*   sR  = (int*)(S + SM_META);
    int*   sC  = (int*)(S + SM_META + 512);
    float* sSq = (float*)(S + SM_META + 1024);
    float* sDx = (float*)(S + SM_META + 1536);
    float* sDy = (float*)(S + SM_META + 2048);
    float* sDz = (float*)(S + SM_META + 2560);
    float* sPart = (float*)(S + SM_META + 3072);  // [2][128]

    // stage weight images once
    {
        const uint4* a = (const uint4*)g_imgW2;
        const uint4* b = (const uint4*)g_imgC1;
        uint4* wa = (uint4*)(S + SM_W2);
        uint4* wb = (uint4*)(S + SM_C1);
        for (int i = tid; i < 4096; i += 256) wa[i] = a[i];
        for (int i = tid; i < 2048; i += 256) wb[i] = b[i];
    }

    const float* w256 = eW1 + 256 * HD;
    // gather mapping: 2 threads per edge
    const int eg = tid >> 1;
    const int kb = (tid & 1) * 64;
    const int gMatom = eg >> 4;
    const int gEloc  = eg & 15;
    const int gLaneB = (gEloc & 7) * 4;
    const int gRegB  = gEloc >> 3;
    // mma tile mapping
    const int mA0 = (w & 3) * 2;       // first matom (of rows)
    const int nA0 = (w >> 2) * 8;      // first natom (of cols)
    const int rowT = lane >> 2;        // 0..7
    const int colJ = (lane & 3) * 2;   // 0,2,4,6

    for (int t = blockIdx.x; t < numTiles; t += gridDim.x) {
        const int base = t * ETILE;
        __syncthreads();   // protect SMEM reuse across tiles

        if (tid < ETILE) {
            int e = base + tid;
            int r = eidx[e];
            int c = eidx[E + e];
            float dx = pos[r * 3 + 0] - pos[c * 3 + 0];
            float dy = pos[r * 3 + 1] - pos[c * 3 + 1];
            float dz = pos[r * 3 + 2] - pos[c * 3 + 2];
            sR[tid] = r; sC[tid] = c;
            sSq[tid] = dx * dx + dy * dy + dz * dz;
            sDx[tid] = dx; sDy[tid] = dy; sDz[tid] = dz;
        }
        __syncthreads();

        // ---- gather + silu + bf16-split into fragment-packed A image
        {
            int r = sR[eg], c = sC[eg];
            float sq = sSq[eg];
            #pragma unroll 4
            for (int g = 0; g < 16; g++) {
                int k = kb + g * 4;
                float4 P = __ldg((const float4*)&g_P[(size_t)r * HD + k]);
                float4 Q = __ldg((const float4*)&g_Q[(size_t)c * HD + k]);
                float4 W = __ldg((const float4*)&w256[k]);
                float4 B = __ldg((const float4*)&eb1[k]);
                float v[4];
                v[0] = silu(P.x + Q.x + sq * W.x + B.x);
                v[1] = silu(P.y + Q.y + sq * W.y + B.y);
                v[2] = silu(P.z + Q.z + sq * W.z + B.z);
                v[3] = silu(P.w + Q.w + sq * W.w + B.w);
                #pragma unroll
                for (int jp = 0; jp < 2; jp++) {
                    int k0 = k + 2 * jp;
                    int kl = k0 & 15;
                    unsigned laneD = (unsigned)(gLaneB + ((kl & 7) >> 1));
                    unsigned regD  = (unsigned)(gRegB + ((kl >> 3) << 1));
                    unsigned slot = (((unsigned)(gMatom * 8 + (k0 >> 4)) * 32u + laneD) * 16u)
                                  + regD * 4u;
                    __nv_bfloat16 h0, h1, l0, l1;
                    bfsplit(v[2 * jp], h0, l0);
                    bfsplit(v[2 * jp + 1], h1, l1);
                    *(unsigned*)(S + SM_A + slot)          = bfpack(h0, h1);
                    *(unsigned*)(S + SM_A + 32768 + slot)  = bfpack(l0, l1);
                }
            }
        }
        __syncthreads();

        float acc[2][8][4];

        // ---- GEMM1: D1 = T @ eW2  (3 bf16 passes: hh, h*lo, lo*h)
        #pragma unroll
        for (int mi = 0; mi < 2; mi++)
            #pragma unroll
            for (int ni = 0; ni < 8; ni++)
                #pragma unroll
                for (int q = 0; q < 4; q++) acc[mi][ni][q] = 0.f;

        #pragma unroll
        for (int pass = 0; pass < 3; pass++) {
            unsigned aBase = SM_A  + ((pass == 2) ? 32768u : 0u);
            unsigned bBase = SM_W2 + ((pass == 1) ? 32768u : 0u);
            #pragma unroll
            for (int ks = 0; ks < 8; ks++) {
                uint4 a0 = *(const uint4*)(S + aBase
                          + (((mA0 + 0) * 8 + ks) * 32 + lane) * 16);
                uint4 a1 = *(const uint4*)(S + aBase
                          + (((mA0 + 1) * 8 + ks) * 32 + lane) * 16);
                uint2 bv[8];
                #pragma unroll
                for (int ni = 0; ni < 8; ni++)
                    bv[ni] = *(const uint2*)(S + bBase
                             + (((nA0 + ni) * 8 + ks) * 32 + lane) * 8);
                #pragma unroll
                for (int ni = 0; ni < 8; ni++) {
                    mma_bf16(acc[0][ni], a0, bv[ni]);
                    mma_bf16(acc[1][ni], a1, bv[ni]);
                }
            }
        }

        // ---- epilogue 1: m = silu(D1 + eb2); scatter; repack into A-hi
        #pragma unroll
        for (int mi = 0; mi < 2; mi++) {
            int e0r = (w & 3) * 32 + mi * 16 + rowT;
            int e1r = e0r + 8;
            size_t rb0 = (size_t)sR[e0r] * HD;
            size_t rb1 = (size_t)sR[e1r] * HD;
            #pragma unroll
            for (int ni = 0; ni < 8; ni++) {
                int n = (w >> 2) * 64 + ni * 8 + colJ;
                float m00 = silu(acc[mi][ni][0] + __ldg(&eb2[n]));
                float m01 = silu(acc[mi][ni][1] + __ldg(&eb2[n + 1]));
                float m10 = silu(acc[mi][ni][2] + __ldg(&eb2[n]));
                float m11 = silu(acc[mi][ni][3] + __ldg(&eb2[n + 1]));
                red_add_v2(&g_mi[rb0 + n], m00, m01);
                red_add_v2(&g_mi[rb1 + n], m10, m11);
                acc[mi][ni][0] = m00; acc[mi][ni][1] = m01;
                acc[mi][ni][2] = m10; acc[mi][ni][3] = m11;
            }
        }
        __syncthreads();   // all GEMM1 reads of A image complete

        #pragma unroll
        for (int mi = 0; mi < 2; mi++) {
            #pragma unroll
            for (int ni = 0; ni < 8; ni++) {
                unsigned kstepD = (unsigned)((w >> 2) * 4 + (ni >> 1));
                unsigned slotB = (((unsigned)((mA0 + mi) * 8) + kstepD) * 32u
                                  + (unsigned)lane) * 16u;
                unsigned regLo = (unsigned)((ni & 1) << 1);      // rows rowT
                unsigned regHi = regLo + 1u;                      // rows rowT+8
                *(unsigned*)(S + SM_A + slotB + regLo * 4u)
                    = bfpack(__float2bfloat16(acc[mi][ni][0]),
                             __float2bfloat16(acc[mi][ni][1]));
                *(unsigned*)(S + SM_A + slotB + regHi * 4u)
                    = bfpack(__float2bfloat16(acc[mi][ni][2]),
                             __float2bfloat16(acc[mi][ni][3]));
            }
        }
        __syncthreads();

        // ---- GEMM2: D2 = M @ cW1  (single bf16 pass)
        #pragma unroll
        for (int mi = 0; mi < 2; mi++)
            #pragma unroll
            for (int ni = 0; ni < 8; ni++)
                #pragma unroll
                for (int q = 0; q < 4; q++) acc[mi][ni][q] = 0.f;

        #pragma unroll
        for (int ks = 0; ks < 8; ks++) {
            uint4 a0 = *(const uint4*)(S + SM_A
                      + (((mA0 + 0) * 8 + ks) * 32 + lane) * 16);
            uint4 a1 = *(const uint4*)(S + SM_A
                      + (((mA0 + 1) * 8 + ks) * 32 + lane) * 16);
            uint2 bv[8];
            #pragma unroll
            for (int ni = 0; ni < 8; ni++)
                bv[ni] = *(const uint2*)(S + SM_C1
                         + (((nA0 + ni) * 8 + ks) * 32 + lane) * 8);
            #pragma unroll
            for (int ni = 0; ni < 8; ni++) {
                mma_bf16(acc[0][ni], a0, bv[ni]);
                mma_bf16(acc[1][ni], a1, bv[ni]);
            }
        }

        // ---- epilogue 2: cw partial = silu(D2 + cb1) . cW2
        #pragma unroll
        for (int mi = 0; mi < 2; mi++) {
            float s0 = 0.f, s1 = 0.f;
            #pragma unroll
            for (int ni = 0; ni < 8; ni++) {
                int n = (w >> 2) * 64 + ni * 8 + colJ;
                float cb0 = __ldg(&cb1[n]),  cb1v = __ldg(&cb1[n + 1]);
                float cw0 = __ldg(&cW2[n]),  cw1v = __ldg(&cW2[n + 1]);
                s0 += silu(acc[mi][ni][0] + cb0) * cw0
                    + silu(acc[mi][ni][1] + cb1v) * cw1v;
                s1 += silu(acc[mi][ni][2] + cb0) * cw0
                    + silu(acc[mi][ni][3] + cb1v) * cw1v;
            }
            s0 += __shfl_xor_sync(0xFFFFFFFFu, s0, 1);
            s0 += __shfl_xor_sync(0xFFFFFFFFu, s0, 2);
            s1 += __shfl_xor_sync(0xFFFFFFFFu, s1, 1);
            s1 += __shfl_xor_sync(0xFFFFFFFFu, s1, 2);
            if ((lane & 3) == 0) {
                int e0r = (w & 3) * 32 + mi * 16 + rowT;
                sPart[(w >> 2) * 128 + e0r]     = s0;
                sPart[(w >> 2) * 128 + e0r + 8] = s1;
            }
        }
        __syncthreads();

        if (tid < ETILE) {
            float cw = sPart[tid] + sPart[128 + tid];
            float inv = rsqrtf(sSq[tid] + 1e-8f);
            float wgt = cw * inv;
            int r = sR[tid];
            atomicAdd(&g_psum[r * 3 + 0], sDx[tid] * wgt);
            atomicAdd(&g_psum[r * 3 + 1], sDy[tid] * wgt);
            atomicAdd(&g_psum[r * 3 + 2], sDz[tid] * wgt);
            atomicAdd(&g_cnt[r], 1.0f);
        }
    }
}

// ---------------------------------------------------------------- node out (R6, f32x2)
__device__ __forceinline__ void fma2(unsigned long long& acc,
                                     unsigned long long a, unsigned long long b) {
    asm("fma.rn.f32x2 %0, %1, %2, %0;" : "+l"(acc) : "l"(a), "l"(b));
}
__device__ __forceinline__ unsigned long long dup2(float x) {
    unsigned long long r;
    asm("mov.b64 %0, {%1, %1};" : "=l"(r) : "f"(x));
    return r;
}
__device__ __forceinline__ void lds_v2u64(unsigned long long& a, unsigned long long& b,
                                          unsigned addr) {
    asm volatile("ld.shared.v2.b64 {%0, %1}, [%2];" : "=l"(a), "=l"(b) : "r"(addr));
}
__device__ __forceinline__ float f2lo(unsigned long long v) {
    return __uint_as_float((unsigned)(v & 0xFFFFFFFFull));
}
__device__ __forceinline__ float f2hi(unsigned long long v) {
    return __uint_as_float((unsigned)(v >> 32));
}

__global__ __launch_bounds__(128) void node_out_kernel(
    const float* __restrict__ h, const float* __restrict__ pos,
    const float* __restrict__ nW1, const float* __restrict__ nb1,
    const float* __restrict__ nW2, const float* __restrict__ nb2,
    float* __restrict__ outH, float* __restrict__ outP, int N)
{
    __shared__ __align__(16) float2 sXp[16 * 2 * HD];

    const int base = blockIdx.x * 32;
    const int tid = threadIdx.x;

    for (int idx = tid; idx < 16 * (2 * HD / 4); idx += 128) {
        int p = idx >> 6, kg = idx & 63, k = kg << 2;
        int n0 = base + 2 * p, n1 = n0 + 1;
        float4 a, b;
        if (k < HD) {
            a = __ldg((const float4*)&h[(size_t)n0 * HD + k]);
            b = __ldg((const float4*)&h[(size_t)n1 * HD + k]);
        } else {
            a = *(const float4*)&g_mi[(size_t)n0 * HD + (k - HD)];
            b = *(const float4*)&g_mi[(size_t)n1 * HD + (k - HD)];
        }
        *(float4*)&sXp[p * 2 * HD + k]     = make_float4(a.x, b.x, a.y, b.y);
        *(float4*)&sXp[p * 2 * HD + k + 2] = make_float4(a.z, b.z, a.w, b.w);
    }
    __syncthreads();

    const int lane = tid & 31;
    const int warp = tid >> 5;
    const int jj = lane * 4;
    const int p0 = warp * 4;
    const unsigned x0 = smem_u32(sXp) + (unsigned)(p0 * 2 * HD) * 8u;

    {
        unsigned long long acc[4][4];
        #pragma unroll
        for (int p = 0; p < 4; p++)
            #pragma unroll
            for (int c = 0; c < 4; c++) acc[p][c] = 0ull;

        #pragma unroll 2
        for (int kk = 0; kk < 2 * HD; kk += 2) {
            float4 wA = __ldg((const float4*)&nW1[(kk + 0) * HD + jj]);
            float4 wB = __ldg((const float4*)&nW1[(kk + 1) * HD + jj]);
            unsigned long long wa0 = dup2(wA.x), wa1 = dup2(wA.y),
                               wa2 = dup2(wA.z), wa3 = dup2(wA.w);
            unsigned long long wb0 = dup2(wB.x), wb1 = dup2(wB.y),
                               wb2 = dup2(wB.z), wb3 = dup2(wB.w);
            #pragma unroll
            for (int p = 0; p < 4; p++) {
                unsigned long long t0, t1;
                lds_v2u64(t0, t1, x0 + (unsigned)(p * 2 * HD + kk) * 8u);
                fma2(acc[p][0], t0, wa0);
                fma2(acc[p][1], t0, wa1);
                fma2(acc[p][2], t0, wa2);
                fma2(acc[p][3], t0, wa3);
                fma2(acc[p][0], t1, wb0);
                fma2(acc[p][1], t1, wb1);
                fma2(acc[p][2], t1, wb2);
                fma2(acc[p][3], t1, wb3);
            }
        }
        __syncwarp();
        float4 b1 = *(const float4*)&nb1[jj];
        float bv[4] = { b1.x, b1.y, b1.z, b1.w };
        #pragma unroll
        for (int p = 0; p < 4; p++) {
            float4 A = make_float4(silu(f2lo(acc[p][0]) + bv[0]),
                                   silu(f2hi(acc[p][0]) + bv[0]),
                                   silu(f2lo(acc[p][1]) + bv[1]),
                                   silu(f2hi(acc[p][1]) + bv[1]));
            float4 B = make_float4(silu(f2lo(acc[p][2]) + bv[2]),
                                   silu(f2hi(acc[p][2]) + bv[2]),
                                   silu(f2lo(acc[p][3]) + bv[3]),
                                   silu(f2hi(acc[p][3]) + bv[3]));
            *(float4*)&sXp[(p0 + p) * 2 * HD + jj]     = A;
            *(float4*)&sXp[(p0 + p) * 2 * HD + jj + 2] = B;
        }
    }
    __syncwarp();

    {
        unsigned long long acc[4][4];
        #pragma unroll
        for (int p = 0; p < 4; p++)
            #pragma unroll
            for (int c = 0; c < 4; c++) acc[p][c] = 0ull;

        #pragma unroll 2
        for (int kk = 0; kk < HD; kk += 2) {
            float4 wA = __ldg((const float4*)&nW2[(kk + 0) * HD + jj]);
            float4 wB = __ldg((const float4*)&nW2[(kk + 1) * HD + jj]);
            unsigned long long wa0 = dup2(wA.x), wa1 = dup2(wA.y),
                               wa2 = dup2(wA.z), wa3 = dup2(wA.w);
            unsigned long long wb0 = dup2(wB.x), wb1 = dup2(wB.y),
                               wb2 = dup2(wB.z), wb3 = dup2(wB.w);
            #pragma unroll
            for (int p = 0; p < 4; p++) {
                unsigned long long t0, t1;
                lds_v2u64(t0, t1, x0 + (unsigned)(p * 2 * HD + kk) * 8u);
                fma2(acc[p][0], t0, wa0);
                fma2(acc[p][1], t0, wa1);
                fma2(acc[p][2], t0, wa2);
                fma2(acc[p][3], t0, wa3);
                fma2(acc[p][0], t1, wb0);
                fma2(acc[p][1], t1, wb1);
                fma2(acc[p][2], t1, wb2);
                fma2(acc[p][3], t1, wb3);
            }
        }
        float4 b2 = *(const float4*)&nb2[jj];
        #pragma unroll
        for (int p = 0; p < 4; p++) {
            int n0 = base + 2 * (p0 + p), n1 = n0 + 1;
            float4 h0 = __ldg((const float4*)&h[(size_t)n0 * HD + jj]);
            float4 h1 = __ldg((const float4*)&h[(size_t)n1 * HD + jj]);
            float4 o0 = make_float4(h0.x + f2lo(acc[p][0]) + b2.x,
                                    h0.y + f2lo(acc[p][1]) + b2.y,
                                    h0.z + f2lo(acc[p][2]) + b2.z,
                                    h0.w + f2lo(acc[p][3]) + b2.w);
            float4 o1 = make_float4(h1.x + f2hi(acc[p][0]) + b2.x,
                                    h1.y + f2hi(acc[p][1]) + b2.y,
                                    h1.z + f2hi(acc[p][2]) + b2.z,
                                    h1.w + f2hi(acc[p][3]) + b2.w);
            *(float4*)&outH[(size_t)n0 * HD + jj] = o0;
            *(float4*)&outH[(size_t)n1 * HD + jj] = o1;
        }
    }

    if (tid < 32) {
        int n = base + tid;
        float c = fmaxf(g_cnt[n], 1.0f);
        outP[n * 3 + 0] = pos[n * 3 + 0] + g_psum[n * 3 + 0] / c;
        outP[n * 3 + 1] = pos[n * 3 + 1] + g_psum[n * 3 + 1] / c;
        outP[n * 3 + 2] = pos[n * 3 + 2] + g_psum[n * 3 + 2] / c;
    }
}

// ---------------------------------------------------------------- launch
extern "C" void kernel_launch(void* const* d_in, const int* in_sizes, int n_in,
                              void* d_out, int out_size)
{
    const float* h    = (const float*)d_in[0];
    const float* pos  = (const float*)d_in[1];
    const int*   eidx = (const int*)d_in[2];
    const float* eW1  = (const float*)d_in[3];
    const float* eb1  = (const float*)d_in[4];
    const float* eW2  = (const float*)d_in[5];
    const float* eb2  = (const float*)d_in[6];
    const float* cW1  = (const float*)d_in[7];
    const float* cb1  = (const float*)d_in[8];
    const float* cW2  = (const float*)d_in[9];
    const float* nW1  = (const float*)d_in[10];
    const float* nb1  = (const float*)d_in[11];
    const float* nW2  = (const float*)d_in[12];
    const float* nb2  = (const float*)d_in[13];

    const int N = in_sizes[0] / HD;
    const int E = in_sizes[2] / 2;

    float* outH = (float*)d_out;
    float* outP = outH + (size_t)N * HD;

    cudaFuncSetAttribute(edge_kernel, cudaFuncAttributeMaxDynamicSharedMemorySize,
                         EDGE_SMEM);

    zero_kernel<<<(N * (HD + 4) + 255) / 256, 256>>>(N);
    prep_weights_kernel<<<(HD * HD + 255) / 256, 256>>>(eW2, cW1);
    node_pre_kernel<<<(N + NTILE - 1) / NTILE, 256>>>(h, eW1, N);
    edge_kernel<<<152, 256, EDGE_SMEM>>>(pos, eidx, eW1, eb1, eb2, cb1, cW2,
                                         N, E, E / ETILE);
    node_out_kernel<<<N / 32, 128>>>(h, pos, nW1, nb1, nW2, nb2, outH, outP, N);
}